// round 8
// baseline (speedup 1.0000x reference)
#include <cuda_runtime.h>

#define HW   262144            // 512*512
#define NB   8
#define NC   64
#define G    16
#define NCELLS (G*G*G)         // 4096
#define EPS  1e-4f
#define TPB  256
#define GRID 760               // persistent: 5 CTAs/SM

// Cell record (8B): byte0 = count (255 = fallback), bytes1..7 = candidate ids,
// padded to 7 entries with candidate[0] (duplicates can't win under strict <).
__device__ uint2 g_cells[NCELLS];

// ---------------- LUT build: exact candidate superset per cell ----------------
__global__ void build_lut(const float* __restrict__ pal)
{
    __shared__ float3 spal[NC];
    if (threadIdx.x < NC) {
        spal[threadIdx.x] = make_float3(pal[3*threadIdx.x],
                                        pal[3*threadIdx.x+1],
                                        pal[3*threadIdx.x+2]);
    }
    __syncthreads();

    int cell = blockIdx.x * blockDim.x + threadIdx.x;
    if (cell >= NCELLS) return;
    int cx = (cell >> 8) & 15, cy = (cell >> 4) & 15, cz = cell & 15;
    const float inv = 1.0f / G;
    float lox = cx * inv, hix = lox + inv;
    float loy = cy * inv, hiy = loy + inv;
    float loz = cz * inv, hiz = loz + inv;

    // threshold = min over colors of (max sq distance from anywhere in the box)
    float thr = 3.4e38f;
    #pragma unroll 8
    for (int k = 0; k < NC; ++k) {
        float3 c = spal[k];
        float dx = fmaxf(c.x - lox, hix - c.x);
        float dy = fmaxf(c.y - loy, hiy - c.y);
        float dz = fmaxf(c.z - loz, hiz - c.z);
        thr = fminf(thr, fmaf(dx,dx, fmaf(dy,dy, dz*dz)));
    }
    thr += EPS;   // margin >> fp ordering noise: every possible fp winner kept

    unsigned int cand[8];
    int cnt = 0;
    #pragma unroll 8
    for (int k = 0; k < NC; ++k) {             // ascending k: tie-break preserved
        float3 c = spal[k];
        float dx = fmaxf(fmaxf(lox - c.x, c.x - hix), 0.0f);
        float dy = fmaxf(fmaxf(loy - c.y, c.y - hiy), 0.0f);
        float dz = fmaxf(fmaxf(loz - c.z, c.z - hiz), 0.0f);
        float dmin = fmaf(dx,dx, fmaf(dy,dy, dz*dz));
        if (dmin <= thr) { if (cnt < 8) cand[cnt] = (unsigned)k; cnt++; }
    }

    uint2 rec;
    if (cnt > 7) {
        rec = make_uint2(255u, 0u);
    } else {
        unsigned long long w = (unsigned)cnt;
        #pragma unroll
        for (int j = 0; j < 7; ++j) {
            unsigned kk = (j < cnt) ? cand[j] : cand[0];   // pad with first
            w |= (unsigned long long)kk << (8*(j+1));
        }
        rec = make_uint2((unsigned)w, (unsigned)(w >> 32));
    }
    g_cells[cell] = rec;
}

// ---------------- main kernel ----------------
extern __shared__ uint2 s_raw2[];

__device__ __forceinline__ void eval_cand(
    int k, float r, float g, float b,
    const float4* __restrict__ sp, float& bd, int& bi)
{
    float4 c = sp[k];
    float d = fmaf(r, c.x, fmaf(g, c.y, fmaf(b, c.z, c.w)));  // identical rounding to R1
    if (d < bd) { bd = d; bi = k; }                           // strict <: first-min wins
}

__device__ __forceinline__ int quantize_px(
    float r, float g, float b,
    const uint2* __restrict__ cells,
    const float4* __restrict__ sp)
{
    // *16 power-of-2 scale: exact cell assignment. fminf guards r==1.0 edge.
    int ix = (int)fminf(r * 16.0f, 15.0f);
    int iy = (int)fminf(g * 16.0f, 15.0f);
    int iz = (int)fminf(b * 16.0f, 15.0f);
    uint2 rec = cells[(ix << 8) | (iy << 4) | iz];
    unsigned int cnt = rec.x & 0xffu;

    float bd = 3.4e38f; int bi = 0;
    if (cnt != 255u) {
        // fixed 7 candidates, fully unrolled: no divergence, 7-wide LDS MLP
        eval_cand((int)((rec.x >>  8) & 0xffu), r, g, b, sp, bd, bi);
        eval_cand((int)((rec.x >> 16) & 0xffu), r, g, b, sp, bd, bi);
        eval_cand((int)( rec.x >> 24        ), r, g, b, sp, bd, bi);
        eval_cand((int)( rec.y        & 0xffu), r, g, b, sp, bd, bi);
        eval_cand((int)((rec.y >>  8) & 0xffu), r, g, b, sp, bd, bi);
        eval_cand((int)((rec.y >> 16) & 0xffu), r, g, b, sp, bd, bi);
        eval_cand((int)( rec.y >> 24        ), r, g, b, sp, bd, bi);
    } else {
        #pragma unroll 8
        for (int k = 0; k < NC; ++k) eval_cand(k, r, g, b, sp, bd, bi);
    }
    return bi;
}

__global__ __launch_bounds__(TPB, 5) void color_reduce_kernel(
    const float* __restrict__ x,
    const float* __restrict__ pal,
    float* __restrict__ out)
{
    uint2*  cells = s_raw2;                        // 4096 * 8B = 32KB
    float4* sp    = (float4*)(s_raw2 + NCELLS);    // {-2r,-2g,-2b,||c||^2} : 1KB

    int t = threadIdx.x;
    #pragma unroll
    for (int i = t; i < NCELLS; i += TPB) cells[i] = g_cells[i];
    if (t < NC) {
        float r = pal[3*t], g = pal[3*t+1], b = pal[3*t+2];
        sp[t] = make_float4(-2.0f*r, -2.0f*g, -2.0f*b, fmaf(r,r, fmaf(g,g, b*b)));
    }
    __syncthreads();

    const int nquads = NB * HW / 4;                // 524288
    for (int q = blockIdx.x * TPB + t; q < nquads; q += GRID * TPB) {
        int bIdx = q >> 16;
        int i    = (q & 65535) * 4;
        size_t base = (size_t)bIdx * (3 * HW) + i;

        float4 px = *(const float4*)(x + base);
        float4 py = *(const float4*)(x + base + HW);
        float4 pz = *(const float4*)(x + base + 2 * HW);

        int b0 = quantize_px(px.x, py.x, pz.x, cells, sp);
        int b1 = quantize_px(px.y, py.y, pz.y, cells, sp);
        int b2 = quantize_px(px.z, py.z, pz.z, cells, sp);
        int b3 = quantize_px(px.w, py.w, pz.w, cells, sp);

        // recover raw color exactly: -0.5 * (-2c)
        float4 c0 = sp[b0], c1 = sp[b1], c2 = sp[b2], c3 = sp[b3];
        *(float4*)(out + base) =
            make_float4(-0.5f*c0.x, -0.5f*c1.x, -0.5f*c2.x, -0.5f*c3.x);
        *(float4*)(out + base + HW) =
            make_float4(-0.5f*c0.y, -0.5f*c1.y, -0.5f*c2.y, -0.5f*c3.y);
        *(float4*)(out + base + 2*HW) =
            make_float4(-0.5f*c0.z, -0.5f*c1.z, -0.5f*c2.z, -0.5f*c3.z);
    }
}

extern "C" void kernel_launch(void* const* d_in, const int* in_sizes, int n_in,
                              void* d_out, int out_size)
{
    const float* x   = (const float*)d_in[0];
    const float* pal = (const float*)d_in[1];
    float*       out = (float*)d_out;

    const int smem_bytes = NCELLS * 8 + NC * 16;   // 33792 < 48KB default
    build_lut<<<NCELLS / TPB, TPB>>>(pal);
    color_reduce_kernel<<<GRID, TPB, smem_bytes>>>(x, pal, out);
}

// round 12
// speedup vs baseline: 1.4604x; 1.4604x over previous
#include <cuda_runtime.h>

#define HW   262144            // 512*512
#define NB   8
#define NC   64
#define G    16
#define NCELLS (G*G*G)         // 4096
#define EPS  1e-4f
#define TPB  256
#define GRID 760               // persistent: 5 CTAs/SM * 152 SMs

typedef unsigned long long ull;

// Tier 1 (8B, smem): byte0 = cnt (<=7) | cnt 8..16 (overflow) | 255 (full scan)
//                    bytes 1..7 = inline candidate ids
__device__ uint2 g_cells[NCELLS];
// Tier 2 (16B, global, L1/L2-resident): 16 candidate ids for cells with cnt 8..16
__device__ uint4 g_overflow[NCELLS];

// ---------------- LUT build: exact candidate superset per cell ----------------
__global__ void build_lut(const float* __restrict__ pal)
{
    __shared__ float3 spal[NC];
    if (threadIdx.x < NC)
        spal[threadIdx.x] = make_float3(pal[3*threadIdx.x],
                                        pal[3*threadIdx.x+1],
                                        pal[3*threadIdx.x+2]);
    __syncthreads();

    int cell = blockIdx.x * blockDim.x + threadIdx.x;
    if (cell >= NCELLS) return;
    int cx = (cell >> 8) & 15, cy = (cell >> 4) & 15, cz = cell & 15;
    const float inv = 1.0f / G;
    float lox = cx * inv, hix = lox + inv;
    float loy = cy * inv, hiy = loy + inv;
    float loz = cz * inv, hiz = loz + inv;

    // threshold = min over colors of (max sq distance from anywhere in the box)
    float thr = 3.4e38f;
    #pragma unroll 8
    for (int k = 0; k < NC; ++k) {
        float3 c = spal[k];
        float dx = fmaxf(c.x - lox, hix - c.x);
        float dy = fmaxf(c.y - loy, hiy - c.y);
        float dz = fmaxf(c.z - loz, hiz - c.z);
        thr = fminf(thr, fmaf(dx,dx, fmaf(dy,dy, dz*dz)));
    }
    thr += EPS;   // margin >> fp ordering noise: every possible fp winner kept

    unsigned cand[16];
    int cnt = 0;
    #pragma unroll 8
    for (int k = 0; k < NC; ++k) {             // ascending k: tie-break preserved
        float3 c = spal[k];
        float dx = fmaxf(fmaxf(lox - c.x, c.x - hix), 0.0f);
        float dy = fmaxf(fmaxf(loy - c.y, c.y - hiy), 0.0f);
        float dz = fmaxf(fmaxf(loz - c.z, c.z - hiz), 0.0f);
        float dmin = fmaf(dx,dx, fmaf(dy,dy, dz*dz));
        if (dmin <= thr) { if (cnt < 16) cand[cnt] = (unsigned)k; cnt++; }
    }

    uint2 rec;
    if (cnt <= 7) {
        ull w = (unsigned)cnt;
        #pragma unroll
        for (int j = 0; j < 7; ++j)
            w |= (ull)((j < cnt) ? cand[j] : 0u) << (8*(j+1));
        rec = make_uint2((unsigned)w, (unsigned)(w >> 32));
    } else if (cnt <= 16) {
        rec = make_uint2((unsigned)cnt, 0u);
        ull wa = 0, wb = 0;
        #pragma unroll
        for (int j = 0; j < 8; ++j) {
            wa |= (ull)((j     < cnt) ? cand[j]   : 0u) << (8*j);
            wb |= (ull)((j + 8 < cnt) ? cand[j+8] : 0u) << (8*j);
        }
        g_overflow[cell] = make_uint4((unsigned)wa, (unsigned)(wa >> 32),
                                      (unsigned)wb, (unsigned)(wb >> 32));
    } else {
        rec = make_uint2(255u, 0u);            // exact full-scan fallback
    }
    g_cells[cell] = rec;
}

// ---------------- main kernel ----------------
extern __shared__ uint2 s_raw2[];

__device__ __forceinline__ void eval_cand(
    int k, float r, float g, float b,
    const float4* __restrict__ sp, float& bd, int& bi)
{
    float4 c = sp[k];
    float d = fmaf(r, c.x, fmaf(g, c.y, fmaf(b, c.z, c.w)));  // identical rounding to R1
    if (d < bd) { bd = d; bi = k; }                           // strict <: first-min wins
}

__device__ __forceinline__ int quantize_px(
    float r, float g, float b,
    const uint2* __restrict__ cells,
    const float4* __restrict__ sp)
{
    // *16 is a power-of-2 scale: exact. fminf guards the x==1.0 edge case.
    int ix = (int)fminf(r * 16.0f, 15.0f);
    int iy = (int)fminf(g * 16.0f, 15.0f);
    int iz = (int)fminf(b * 16.0f, 15.0f);
    int ci = (ix << 8) | (iy << 4) | iz;
    uint2 rec = cells[ci];
    unsigned cnt = rec.x & 0xffu;

    float bd = 3.4e38f; int bi = 0;
    if (cnt <= 7u) {
        ull w = (((ull)rec.y << 32) | rec.x) >> 8;
        for (unsigned j = 0; j < cnt; ++j) {
            eval_cand((int)(w & 0xff), r, g, b, sp, bd, bi);
            w >>= 8;
        }
    } else if (cnt != 255u) {
        uint4 ov = __ldg(&g_overflow[ci]);
        ull wa = ((ull)ov.y << 32) | ov.x;
        ull wb = ((ull)ov.w << 32) | ov.z;
        unsigned n0 = cnt < 8u ? cnt : 8u;
        for (unsigned j = 0; j < n0; ++j) {
            eval_cand((int)(wa & 0xff), r, g, b, sp, bd, bi);
            wa >>= 8;
        }
        for (unsigned j = 8; j < cnt; ++j) {
            eval_cand((int)(wb & 0xff), r, g, b, sp, bd, bi);
            wb >>= 8;
        }
    } else {
        #pragma unroll 8
        for (int k = 0; k < NC; ++k) eval_cand(k, r, g, b, sp, bd, bi);
    }
    return bi;
}

__global__ __launch_bounds__(TPB, 5) void color_reduce_kernel(
    const float* __restrict__ x,
    const float* __restrict__ pal,
    float* __restrict__ out)
{
    uint2*  cells = s_raw2;                        // 4096 * 8B = 32KB
    float4* sp    = (float4*)(s_raw2 + NCELLS);    // {-2r,-2g,-2b,||c||^2} : 1KB

    int t = threadIdx.x;
    #pragma unroll
    for (int i = t; i < NCELLS; i += TPB) cells[i] = g_cells[i];
    if (t < NC) {
        float r = pal[3*t], g = pal[3*t+1], b = pal[3*t+2];
        sp[t] = make_float4(-2.0f*r, -2.0f*g, -2.0f*b, fmaf(r,r, fmaf(g,g, b*b)));
    }
    __syncthreads();

    const int nquads = NB * HW / 4;                // 524288
    for (int q = blockIdx.x * TPB + t; q < nquads; q += GRID * TPB) {
        int bIdx = q >> 16;
        int i    = (q & 65535) * 4;
        size_t base = (size_t)bIdx * (3 * HW) + i;

        float4 px = *(const float4*)(x + base);
        float4 py = *(const float4*)(x + base + HW);
        float4 pz = *(const float4*)(x + base + 2 * HW);

        int b0 = quantize_px(px.x, py.x, pz.x, cells, sp);
        int b1 = quantize_px(px.y, py.y, pz.y, cells, sp);
        int b2 = quantize_px(px.z, py.z, pz.z, cells, sp);
        int b3 = quantize_px(px.w, py.w, pz.w, cells, sp);

        // recover raw color exactly: -0.5 * (-2c)
        float4 c0 = sp[b0], c1 = sp[b1], c2 = sp[b2], c3 = sp[b3];
        *(float4*)(out + base) =
            make_float4(-0.5f*c0.x, -0.5f*c1.x, -0.5f*c2.x, -0.5f*c3.x);
        *(float4*)(out + base + HW) =
            make_float4(-0.5f*c0.y, -0.5f*c1.y, -0.5f*c2.y, -0.5f*c3.y);
        *(float4*)(out + base + 2*HW) =
            make_float4(-0.5f*c0.z, -0.5f*c1.z, -0.5f*c2.z, -0.5f*c3.z);
    }
}

extern "C" void kernel_launch(void* const* d_in, const int* in_sizes, int n_in,
                              void* d_out, int out_size)
{
    const float* x   = (const float*)d_in[0];
    const float* pal = (const float*)d_in[1];
    float*       out = (float*)d_out;

    const int smem_bytes = NCELLS * 8 + NC * 16;   // 33792 < 48KB default
    build_lut<<<NCELLS / TPB, TPB>>>(pal);
    color_reduce_kernel<<<GRID, TPB, smem_bytes>>>(x, pal, out);
}

// round 13
// speedup vs baseline: 2.0505x; 1.4040x over previous
#include <cuda_runtime.h>

#define HW   262144            // 512*512
#define NB   8
#define NC   64
#define G    16
#define NCELLS (G*G*G)         // 4096
#define EPS  1e-4f
#define TPB  256
#define GRID 760               // persistent: 5 CTAs/SM * 152 SMs

typedef unsigned long long ull;

// Cell record: 64-bit candidate mask (bit k set => palette color k may win here).
__device__ uint2 g_cells[NCELLS];

// ---------------- LUT build: warp per cell, ballot-based ----------------
__global__ void build_lut(const float* __restrict__ pal)
{
    __shared__ float3 spal[NC];
    if (threadIdx.x < NC)
        spal[threadIdx.x] = make_float3(pal[3*threadIdx.x],
                                        pal[3*threadIdx.x+1],
                                        pal[3*threadIdx.x+2]);
    __syncthreads();

    int warp = (blockIdx.x * TPB + threadIdx.x) >> 5;     // one cell per warp
    int lane = threadIdx.x & 31;
    if (warp >= NCELLS) return;

    int cx = (warp >> 8) & 15, cy = (warp >> 4) & 15, cz = warp & 15;
    const float inv = 1.0f / G;
    float lox = cx * inv, hix = lox + inv;
    float loy = cy * inv, hiy = loy + inv;
    float loz = cz * inv, hiz = loz + inv;

    // per-lane: colors lane and lane+32
    float3 cA = spal[lane], cB = spal[lane + 32];

    // thr = min over colors of (max sq distance from anywhere in the box)
    float dxA = fmaxf(cA.x - lox, hix - cA.x);
    float dyA = fmaxf(cA.y - loy, hiy - cA.y);
    float dzA = fmaxf(cA.z - loz, hiz - cA.z);
    float mA  = fmaf(dxA,dxA, fmaf(dyA,dyA, dzA*dzA));
    float dxB = fmaxf(cB.x - lox, hix - cB.x);
    float dyB = fmaxf(cB.y - loy, hiy - cB.y);
    float dzB = fmaxf(cB.z - loz, hiz - cB.z);
    float mB  = fmaf(dxB,dxB, fmaf(dyB,dyB, dzB*dzB));
    float thr = fminf(mA, mB);
    #pragma unroll
    for (int o = 16; o > 0; o >>= 1)
        thr = fminf(thr, __shfl_xor_sync(0xffffffffu, thr, o));
    thr += EPS;   // margin >> fp ordering noise: every possible fp winner kept

    // candidate test: nearest-point box distance <= thr
    float nxA = fmaxf(fmaxf(lox - cA.x, cA.x - hix), 0.0f);
    float nyA = fmaxf(fmaxf(loy - cA.y, cA.y - hiy), 0.0f);
    float nzA = fmaxf(fmaxf(loz - cA.z, cA.z - hiz), 0.0f);
    bool pA = fmaf(nxA,nxA, fmaf(nyA,nyA, nzA*nzA)) <= thr;
    float nxB = fmaxf(fmaxf(lox - cB.x, cB.x - hix), 0.0f);
    float nyB = fmaxf(fmaxf(loy - cB.y, cB.y - hiy), 0.0f);
    float nzB = fmaxf(fmaxf(loz - cB.z, cB.z - hiz), 0.0f);
    bool pB = fmaf(nxB,nxB, fmaf(nyB,nyB, nzB*nzB)) <= thr;

    unsigned mlo = __ballot_sync(0xffffffffu, pA);        // colors 0..31
    unsigned mhi = __ballot_sync(0xffffffffu, pB);        // colors 32..63
    if (lane == 0) g_cells[warp] = make_uint2(mlo, mhi);
}

// ---------------- main kernel ----------------
extern __shared__ uint2 s_raw2[];

__device__ __forceinline__ void eval_cand(
    int k, float r, float g, float b,
    const float4* __restrict__ sp, float& bd, int& bi)
{
    float4 c = sp[k];
    float d = fmaf(r, c.x, fmaf(g, c.y, fmaf(b, c.z, c.w)));  // identical rounding to R1
    if (d < bd) { bd = d; bi = k; }                           // strict <: first-min wins
}

__device__ __forceinline__ int quantize_px(
    float r, float g, float b,
    const uint2* __restrict__ cells,
    const float4* __restrict__ sp)
{
    // *16 is a power-of-2 scale: exact cell assignment (uniform [0,1) inputs).
    int ix = (int)fminf(r * 16.0f, 15.0f);
    int iy = (int)fminf(g * 16.0f, 15.0f);
    int iz = (int)fminf(b * 16.0f, 15.0f);
    uint2 rec = cells[(ix << 8) | (iy << 4) | iz];

    float bd = 3.4e38f; int bi = 0;
    unsigned m = rec.x;                        // colors 0..31, ascending ffs = tie-break order
    while (m) {
        int k = __ffs(m) - 1;
        m &= m - 1;
        eval_cand(k, r, g, b, sp, bd, bi);
    }
    m = rec.y;                                 // colors 32..63
    while (m) {
        int k = __ffs(m) + 31;
        m &= m - 1;
        eval_cand(k, r, g, b, sp, bd, bi);
    }
    return bi;
}

__global__ __launch_bounds__(TPB, 5) void color_reduce_kernel(
    const float* __restrict__ x,
    const float* __restrict__ pal,
    float* __restrict__ out)
{
    uint2*  cells = s_raw2;                        // 4096 * 8B = 32KB
    float4* sp    = (float4*)(s_raw2 + NCELLS);    // {-2r,-2g,-2b,||c||^2} : 1KB
    float4* sc    = sp + NC;                       // raw colors            : 1KB

    int t = threadIdx.x;
    #pragma unroll
    for (int i = t; i < NCELLS; i += TPB) cells[i] = g_cells[i];
    if (t < NC) {
        float r = pal[3*t], g = pal[3*t+1], b = pal[3*t+2];
        sp[t] = make_float4(-2.0f*r, -2.0f*g, -2.0f*b, fmaf(r,r, fmaf(g,g, b*b)));
        sc[t] = make_float4(r, g, b, 0.0f);
    }
    __syncthreads();

    const int nquads = NB * HW / 4;                // 524288
    for (int q = blockIdx.x * TPB + t; q < nquads; q += GRID * TPB) {
        int bIdx = q >> 16;
        int i    = (q & 65535) * 4;
        size_t base = (size_t)bIdx * (3 * HW) + i;

        float4 px = *(const float4*)(x + base);
        float4 py = *(const float4*)(x + base + HW);
        float4 pz = *(const float4*)(x + base + 2 * HW);

        int b0 = quantize_px(px.x, py.x, pz.x, cells, sp);
        int b1 = quantize_px(px.y, py.y, pz.y, cells, sp);
        int b2 = quantize_px(px.z, py.z, pz.z, cells, sp);
        int b3 = quantize_px(px.w, py.w, pz.w, cells, sp);

        float4 c0 = sc[b0], c1 = sc[b1], c2 = sc[b2], c3 = sc[b3];
        *(float4*)(out + base)          = make_float4(c0.x, c1.x, c2.x, c3.x);
        *(float4*)(out + base + HW)     = make_float4(c0.y, c1.y, c2.y, c3.y);
        *(float4*)(out + base + 2*HW)   = make_float4(c0.z, c1.z, c2.z, c3.z);
    }
}

extern "C" void kernel_launch(void* const* d_in, const int* in_sizes, int n_in,
                              void* d_out, int out_size)
{
    const float* x   = (const float*)d_in[0];
    const float* pal = (const float*)d_in[1];
    float*       out = (float*)d_out;

    const int smem_bytes = NCELLS * 8 + 2 * NC * 16;   // 34816 < 48KB default
    build_lut<<<(NCELLS * 32) / TPB, TPB>>>(pal);      // warp per cell: 512 blocks
    color_reduce_kernel<<<GRID, TPB, smem_bytes>>>(x, pal, out);
}